// round 6
// baseline (speedup 1.0000x reference)
#include <cuda_runtime.h>
#include <cuda_bf16.h>
#include <math.h>

// Problem constants (fixed by the dataset)
#define MAXN 100000
#define MAXE 1600000
#define F 32            // F_IN == F_OUT == 32

// Scratch (static device globals; no allocation allowed)
__device__ int   d_idx64;            // 1 if edge_index is int64, 0 if int32
__device__ float d_deg[MAXN];        // out-degree (sum of w over src)
__device__ int   d_cnt[MAXN];        // in-degree counts -> cursor -> inclusive prefix
__device__ int   d_src[MAXE];        // int32 source indices (unsorted)
__device__ int   d_dst[MAXE];        // int32 dest indices (unsorted)
__device__ float d_w[MAXE];          // weight, zeroed for self loops / bad edges
__device__ int   d_esrc[MAXE];       // src sorted by dst (CSR)
__device__ float d_ecoef[MAXE];      // coef sorted by dst (CSR)

// ---------------------------------------------------------------------------
// f32x2 packed-pipe helpers (sm_103a dual-fp32)
// ---------------------------------------------------------------------------
__device__ __forceinline__ unsigned long long pk2(float lo, float hi) {
    unsigned long long r;
    asm("mov.b64 %0, {%1, %2};" : "=l"(r) : "f"(lo), "f"(hi));
    return r;
}
__device__ __forceinline__ void upk2(unsigned long long v, float& lo, float& hi) {
    asm("mov.b64 {%0, %1}, %2;" : "=f"(lo), "=f"(hi) : "l"(v));
}
__device__ __forceinline__ unsigned long long fma2(unsigned long long a,
                                                   unsigned long long b,
                                                   unsigned long long c) {
    unsigned long long d;
    asm("fma.rn.f32x2 %0, %1, %2, %3;" : "=l"(d) : "l"(a), "l"(b), "l"(c));
    return d;
}

// ---------------------------------------------------------------------------
// K-1: detect edge_index dtype (one warp, parallel probes + ballot).
// ---------------------------------------------------------------------------
__global__ void k_detect(const void* __restrict__ ei, int E, int n) {
    const long long* p = (const long long*)ei;
    int lane = threadIdx.x;
    long long a = p[lane];
    long long b = p[E + lane];
    int bad = (a < 0 || a >= n || b < 0 || b >= n) ? 1 : 0;
    unsigned m = __ballot_sync(0xffffffffu, bad);
    if (lane == 0) d_idx64 = (m == 0u) ? 1 : 0;
}

// ---------------------------------------------------------------------------
// K0: zero deg and cnt
// ---------------------------------------------------------------------------
__global__ void k_zero(int n) {
    int i = blockIdx.x * blockDim.x + threadIdx.x;
    if (i < n) { d_deg[i] = 0.0f; d_cnt[i] = 0; }
}

// ---------------------------------------------------------------------------
// K1: single pass over edge_index:
//   - convert indices to int32 scratch
//   - zero self-loop / OOB weights
//   - deg[src] += w  and  cnt[dst] += 1 (skip dead edges entirely)
// ---------------------------------------------------------------------------
__global__ void k_prep(const void* __restrict__ ei,
                       const float* __restrict__ ew, int E, int n) {
    int e = blockIdx.x * blockDim.x + threadIdx.x;
    if (e >= E) return;
    int s, d;
    if (d_idx64) {
        const long long* p = (const long long*)ei;
        s = (int)p[e];
        d = (int)p[E + e];
    } else {
        const int* p = (const int*)ei;
        s = p[e];
        d = p[E + e];
    }
    float w = ew[e];
    if ((unsigned)s >= (unsigned)n || (unsigned)d >= (unsigned)n) {
        s = 0; d = 0; w = 0.0f;
    }
    if (s == d) w = 0.0f;
    d_src[e] = s;
    d_dst[e] = d;
    d_w[e]   = w;
    if (w != 0.0f) {
        atomicAdd(&d_deg[s], w);
        atomicAdd(&d_cnt[d], 1);
    }
}

// ---------------------------------------------------------------------------
// K2: single-block exclusive scan of cnt (in place -> write cursors)
// ---------------------------------------------------------------------------
__global__ void k_scan(int n) {
    __shared__ int ssum[1024];
    int t = threadIdx.x;
    int per = (n + 1023) >> 10;
    int lo = t * per;
    int hi = min(lo + per, n);
    int sum = 0;
    for (int i = lo; i < hi; i++) sum += d_cnt[i];
    ssum[t] = sum;
    __syncthreads();
    // inclusive Hillis-Steele scan over thread partials
    for (int off = 1; off < 1024; off <<= 1) {
        int v = (t >= off) ? ssum[t - off] : 0;
        __syncthreads();
        ssum[t] += v;
        __syncthreads();
    }
    int run = (t > 0) ? ssum[t - 1] : 0;   // exclusive base for this chunk
    for (int i = lo; i < hi; i++) {
        int c = d_cnt[i];
        d_cnt[i] = run;                    // cursor = exclusive prefix
        run += c;
    }
}

// ---------------------------------------------------------------------------
// K3: reorder edges into CSR-by-dst, computing coefficient inline:
//     coef = -rsqrt(deg[src]) * w * rsqrt(deg[dst])
// After this kernel d_cnt[i] == inclusive prefix (row end for node i).
// ---------------------------------------------------------------------------
__global__ void k_reorder(int E) {
    int e = blockIdx.x * blockDim.x + threadIdx.x;
    if (e >= E) return;
    float w = d_w[e];
    if (w == 0.0f) return;
    int s = d_src[e];
    int d = d_dst[e];
    float ds = d_deg[s], dd = d_deg[d];
    float c = (ds > 0.0f && dd > 0.0f) ? -rsqrtf(ds) * w * rsqrtf(dd) : 0.0f;
    int pos = atomicAdd(&d_cnt[d], 1);
    d_esrc[pos]  = s;
    d_ecoef[pos] = c;
}

// ---------------------------------------------------------------------------
// K4: fused gather (tx1 in registers) + gates + output.
// One warp handles 4 nodes; lane = output feature.
//   tx1[n] = sum over incident edges of coef * x[src]      (gather, no atomics)
//   I = sigmoid(x@Wx[0,0] + tx1@Wx[0,1] + Bi)
//   T = tanh   (x@Wx[2,0] + tx1@Wx[2,1] + Bc)
//   C = I*T
//   O = sigmoid(x@Wx[3,0] + tx1@Wx[3,1] + Bo + wc[2]*C)
//   H = O*tanh(C);  out = relu(H)@lin_w + lin_b
// Gate matvecs use fma.rn.f32x2 (2 nodes per instruction), weights LDS'd
// once per 4 nodes.
// ---------------------------------------------------------------------------
__global__ void k_gather_gates(const float* __restrict__ x,
                               const float* __restrict__ Wx,
                               const float* __restrict__ bx,
                               const float* __restrict__ bh,
                               const float* __restrict__ wc,
                               const float* __restrict__ bgate,
                               const float* __restrict__ linw,
                               const float* __restrict__ linb,
                               float* __restrict__ out, int n) {
    __shared__ float sW[6][F * F];   // Wi0, Wi1, Wc0, Wc1, Wo0, Wo1
    __shared__ float sBi[F], sBc[F], sBo[F], sWc2[F], sLw[F];
    __shared__ float sLb;

    int tid = threadIdx.x;
    for (int i = tid; i < F * F; i += blockDim.x) {
        sW[0][i] = Wx[0 * F * F + i];   // gate i, k=0
        sW[1][i] = Wx[1 * F * F + i];   // gate i, k=1
        sW[2][i] = Wx[4 * F * F + i];   // gate c, k=0
        sW[3][i] = Wx[5 * F * F + i];   // gate c, k=1
        sW[4][i] = Wx[6 * F * F + i];   // gate o, k=0
        sW[5][i] = Wx[7 * F * F + i];   // gate o, k=1
    }
    if (tid < F) {
        sBi[tid]  = bx[0 * F + tid] + bh[0 * F + tid] + bgate[0 * F + tid];
        sBc[tid]  = bx[2 * F + tid] + bh[2 * F + tid] + bgate[2 * F + tid];
        sBo[tid]  = bx[3 * F + tid] + bh[3 * F + tid] + bgate[3 * F + tid];
        sWc2[tid] = wc[2 * F + tid];
        sLw[tid]  = linw[tid];
        if (tid == 0) sLb = linb[0];
    }
    __syncthreads();

    int warp = tid >> 5;
    int lane = tid & 31;
    int base = (blockIdx.x * (blockDim.x >> 5) + warp) * 4;
    if (base >= n) return;

    // -------- gather phase: tx1 for 4 nodes into registers --------
    float xr[4], tr[4];
#pragma unroll
    for (int i = 0; i < 4; i++) {
        int nd = base + i;
        float acc = 0.0f, xv = 0.0f;
        if (nd < n) {                       // warp-uniform condition
            xv = x[nd * F + lane];
            int st = nd ? d_cnt[nd - 1] : 0;
            int en = d_cnt[nd];
            for (int b0 = st; b0 < en; b0 += 32) {
                int j = b0 + lane;
                int   sj = 0;
                float cj = 0.0f;
                if (j < en) { sj = d_esrc[j]; cj = d_ecoef[j]; }
                int m = min(32, en - b0);
                for (int k = 0; k < m; k++) {
                    int   s = __shfl_sync(0xffffffffu, sj, k);
                    float c = __shfl_sync(0xffffffffu, cj, k);
                    acc += c * __ldg(&x[s * F + lane]);
                }
            }
        }
        xr[i] = xv;
        tr[i] = acc;
    }

    // -------- gate phase: packed f32x2, 2 nodes per instruction --------
    float bi = sBi[lane], bc = sBc[lane], bo = sBo[lane];
    unsigned long long ai01 = pk2(bi, bi), ai23 = pk2(bi, bi);
    unsigned long long ac01 = pk2(bc, bc), ac23 = pk2(bc, bc);
    unsigned long long ao01 = pk2(bo, bo), ao23 = pk2(bo, bo);

#pragma unroll
    for (int f = 0; f < F; f++) {
        float w0 = sW[0][f * F + lane];
        float w1 = sW[1][f * F + lane];
        float w2 = sW[2][f * F + lane];
        float w3 = sW[3][f * F + lane];
        float w4 = sW[4][f * F + lane];
        float w5 = sW[5][f * F + lane];
        float xf0 = __shfl_sync(0xffffffffu, xr[0], f);
        float xf1 = __shfl_sync(0xffffffffu, xr[1], f);
        float xf2 = __shfl_sync(0xffffffffu, xr[2], f);
        float xf3 = __shfl_sync(0xffffffffu, xr[3], f);
        float tf0 = __shfl_sync(0xffffffffu, tr[0], f);
        float tf1 = __shfl_sync(0xffffffffu, tr[1], f);
        float tf2 = __shfl_sync(0xffffffffu, tr[2], f);
        float tf3 = __shfl_sync(0xffffffffu, tr[3], f);
        unsigned long long x01 = pk2(xf0, xf1), x23 = pk2(xf2, xf3);
        unsigned long long t01 = pk2(tf0, tf1), t23 = pk2(tf2, tf3);
        unsigned long long W0 = pk2(w0, w0), W1 = pk2(w1, w1);
        unsigned long long W2 = pk2(w2, w2), W3 = pk2(w3, w3);
        unsigned long long W4 = pk2(w4, w4), W5 = pk2(w5, w5);
        ai01 = fma2(x01, W0, fma2(t01, W1, ai01));
        ai23 = fma2(x23, W0, fma2(t23, W1, ai23));
        ac01 = fma2(x01, W2, fma2(t01, W3, ac01));
        ac23 = fma2(x23, W2, fma2(t23, W3, ac23));
        ao01 = fma2(x01, W4, fma2(t01, W5, ao01));
        ao23 = fma2(x23, W4, fma2(t23, W5, ao23));
    }

    float ai[4], ac[4], ao[4];
    upk2(ai01, ai[0], ai[1]); upk2(ai23, ai[2], ai[3]);
    upk2(ac01, ac[0], ac[1]); upk2(ac23, ac[2], ac[3]);
    upk2(ao01, ao[0], ao[1]); upk2(ao23, ao[2], ao[3]);

    float wcl = sWc2[lane], lwl = sLw[lane], lb = sLb;
#pragma unroll
    for (int i = 0; i < 4; i++) {
        int nd = base + i;
        if (nd >= n) break;                  // warp-uniform
        float I = 1.0f / (1.0f + expf(-ai[i]));
        float T = tanhf(ac[i]);
        float C = I * T;
        float O = 1.0f / (1.0f + expf(-(ao[i] + wcl * C)));
        float H = O * tanhf(C);
        float r = fmaxf(H, 0.0f) * lwl;
#pragma unroll
        for (int off = 16; off > 0; off >>= 1)
            r += __shfl_xor_sync(0xffffffffu, r, off);
        if (lane == 0) out[nd] = r + lb;
    }
}

// ---------------------------------------------------------------------------
extern "C" void kernel_launch(void* const* d_in, const int* in_sizes, int n_in,
                              void* d_out, int out_size) {
    const float* x     = (const float*)d_in[0];
    const void*  ei    = d_in[1];
    const float* ew    = (const float*)d_in[2];
    const float* Wx    = (const float*)d_in[3];
    const float* bx    = (const float*)d_in[4];
    // d_in[5] = Wh (dead: H_prev == 0)
    const float* bh    = (const float*)d_in[6];
    const float* wc    = (const float*)d_in[7];
    const float* bgate = (const float*)d_in[8];
    const float* linw  = (const float*)d_in[9];
    const float* linb  = (const float*)d_in[10];
    float*       out   = (float*)d_out;

    const int N = in_sizes[0] / F;
    const int E = in_sizes[2];

    const int B = 256;
    k_detect<<<1, 32>>>(ei, E, N);
    k_zero<<<(N + B - 1) / B, B>>>(N);
    k_prep<<<(E + B - 1) / B, B>>>(ei, ew, E, N);
    k_scan<<<1, 1024>>>(N);
    k_reorder<<<(E + B - 1) / B, B>>>(E);
    // 8 warps/block, 4 nodes/warp -> 32 nodes per block
    k_gather_gates<<<(N + 31) / 32, B>>>(x, Wx, bx, bh, wc, bgate, linw, linb,
                                         out, N);
}

// round 8
// speedup vs baseline: 2.6052x; 2.6052x over previous
#include <cuda_runtime.h>
#include <cuda_bf16.h>
#include <math.h>

// Problem constants (fixed by the dataset)
#define MAXN 100000
#define MAXE 1600000
#define F 32            // F_IN == F_OUT == 32
#define SCAN_B 256      // elements per scan block

// Scratch (static device globals; no allocation allowed)
__device__ int   d_idx64;            // 1 if edge_index is int64, 0 if int32
__device__ float d_deg[MAXN];        // degree -> dinv (after k_scan3)
__device__ int   d_cnt[MAXN];        // counts -> exclusive prefix (cursor) -> inclusive
__device__ int   d_bsum[1024];       // per-block sums for the scan
__device__ int   d_src[MAXE];        // int32 source indices (unsorted)
__device__ int   d_dst[MAXE];        // int32 dest indices (unsorted)
__device__ float d_w[MAXE];          // weight, zeroed for self loops / bad edges
__device__ int   d_esrc[MAXE];       // src sorted by dst (CSR)
__device__ float d_ecoef[MAXE];      // coef sorted by dst (CSR)

// ---------------------------------------------------------------------------
// f32x2 packed-pipe helpers (sm_103a dual-fp32)
// ---------------------------------------------------------------------------
__device__ __forceinline__ unsigned long long pk2(float lo, float hi) {
    unsigned long long r;
    asm("mov.b64 %0, {%1, %2};" : "=l"(r) : "f"(lo), "f"(hi));
    return r;
}
__device__ __forceinline__ void upk2(unsigned long long v, float& lo, float& hi) {
    asm("mov.b64 {%0, %1}, %2;" : "=f"(lo), "=f"(hi) : "l"(v));
}
__device__ __forceinline__ unsigned long long fma2(unsigned long long a,
                                                   unsigned long long b,
                                                   unsigned long long c) {
    unsigned long long d;
    asm("fma.rn.f32x2 %0, %1, %2, %3;" : "=l"(d) : "l"(a), "l"(b), "l"(c));
    return d;
}

// ---------------------------------------------------------------------------
// K-1: detect edge_index dtype (one warp, parallel probes + ballot).
// ---------------------------------------------------------------------------
__global__ void k_detect(const void* __restrict__ ei, int E, int n) {
    const long long* p = (const long long*)ei;
    int lane = threadIdx.x;
    long long a = p[lane];
    long long b = p[E + lane];
    int bad = (a < 0 || a >= n || b < 0 || b >= n) ? 1 : 0;
    unsigned m = __ballot_sync(0xffffffffu, bad);
    if (lane == 0) d_idx64 = (m == 0u) ? 1 : 0;
}

// ---------------------------------------------------------------------------
// K0: zero deg and cnt
// ---------------------------------------------------------------------------
__global__ void k_zero(int n) {
    int i = blockIdx.x * blockDim.x + threadIdx.x;
    if (i < n) { d_deg[i] = 0.0f; d_cnt[i] = 0; }
}

// ---------------------------------------------------------------------------
// K1: single pass over edge_index:
//   - convert indices to int32 scratch
//   - zero self-loop / OOB weights
//   - deg[src] += w  and  cnt[dst] += 1 (skip dead edges entirely)
// ---------------------------------------------------------------------------
__global__ void k_prep(const void* __restrict__ ei,
                       const float* __restrict__ ew, int E, int n) {
    int e = blockIdx.x * blockDim.x + threadIdx.x;
    if (e >= E) return;
    int s, d;
    if (d_idx64) {
        const long long* p = (const long long*)ei;
        s = (int)p[e];
        d = (int)p[E + e];
    } else {
        const int* p = (const int*)ei;
        s = p[e];
        d = p[E + e];
    }
    float w = ew[e];
    if ((unsigned)s >= (unsigned)n || (unsigned)d >= (unsigned)n) {
        s = 0; d = 0; w = 0.0f;
    }
    if (s == d) w = 0.0f;
    d_src[e] = s;
    d_dst[e] = d;
    d_w[e]   = w;
    if (w != 0.0f) {
        atomicAdd(&d_deg[s], w);
        atomicAdd(&d_cnt[d], 1);
    }
}

// ---------------------------------------------------------------------------
// K2a: per-block sums of cnt (SCAN_B elements per block, coalesced)
// ---------------------------------------------------------------------------
__global__ void k_scan1(int n) {
    __shared__ int wsum[SCAN_B / 32];
    int t = threadIdx.x;
    int i = blockIdx.x * SCAN_B + t;
    int v = (i < n) ? d_cnt[i] : 0;
#pragma unroll
    for (int off = 16; off > 0; off >>= 1)
        v += __shfl_down_sync(0xffffffffu, v, off);
    if ((t & 31) == 0) wsum[t >> 5] = v;
    __syncthreads();
    if (t == 0) {
        int s = 0;
#pragma unroll
        for (int j = 0; j < SCAN_B / 32; j++) s += wsum[j];
        d_bsum[blockIdx.x] = s;
    }
}

// ---------------------------------------------------------------------------
// K2b: one block, exclusive scan of per-block sums (nb <= 1024)
// ---------------------------------------------------------------------------
__global__ void k_scan2(int nb) {
    __shared__ int sv[1024];
    int t = threadIdx.x;
    int v = (t < nb) ? d_bsum[t] : 0;
    sv[t] = v;
    __syncthreads();
    for (int off = 1; off < 1024; off <<= 1) {
        int u = (t >= off) ? sv[t - off] : 0;
        __syncthreads();
        sv[t] += u;
        __syncthreads();
    }
    if (t < nb) d_bsum[t] = sv[t] - v;   // exclusive
}

// ---------------------------------------------------------------------------
// K2c: per-block exclusive scan + base -> cursor in d_cnt.
//      Also converts deg -> dinv (fused, after k_prep completed).
// ---------------------------------------------------------------------------
__global__ void k_scan3(int n) {
    __shared__ int wsum[SCAN_B / 32];
    int t = threadIdx.x;
    int lane = t & 31, w = t >> 5;
    int i = blockIdx.x * SCAN_B + t;
    int v = (i < n) ? d_cnt[i] : 0;
    int s = v;
#pragma unroll
    for (int off = 1; off < 32; off <<= 1) {
        int u = __shfl_up_sync(0xffffffffu, s, off);
        if (lane >= off) s += u;
    }
    if (lane == 31) wsum[w] = s;
    __syncthreads();
    if (t == 0) {
        int run = 0;
#pragma unroll
        for (int j = 0; j < SCAN_B / 32; j++) {
            int c = wsum[j]; wsum[j] = run; run += c;
        }
    }
    __syncthreads();
    if (i < n) {
        d_cnt[i] = (s - v) + wsum[w] + d_bsum[blockIdx.x];
        float dg = d_deg[i];
        d_deg[i] = (dg > 0.0f) ? rsqrtf(dg) : 0.0f;
    }
}

// ---------------------------------------------------------------------------
// K3: reorder edges into CSR-by-dst:  coef = -dinv[src] * w * dinv[dst]
// (d_deg already holds dinv.) After this, d_cnt[i] == inclusive prefix.
// ---------------------------------------------------------------------------
__global__ void k_reorder(int E) {
    int e = blockIdx.x * blockDim.x + threadIdx.x;
    if (e >= E) return;
    float w = d_w[e];
    if (w == 0.0f) return;
    int s = d_src[e];
    int d = d_dst[e];
    float c = -d_deg[s] * w * d_deg[d];
    int pos = atomicAdd(&d_cnt[d], 1);
    d_esrc[pos]  = s;
    d_ecoef[pos] = c;
}

// ---------------------------------------------------------------------------
// K4: fused gather (tx1 in registers) + gates + output.
// One warp handles 4 nodes; lane = output feature. Gather inner loop is
// unrolled x4 with zero-padded lanes (4 independent LDGs in flight).
// Gate matvecs use fma.rn.f32x2 (2 nodes per instruction).
// ---------------------------------------------------------------------------
__global__ void k_gather_gates(const float* __restrict__ x,
                               const float* __restrict__ Wx,
                               const float* __restrict__ bx,
                               const float* __restrict__ bh,
                               const float* __restrict__ wc,
                               const float* __restrict__ bgate,
                               const float* __restrict__ linw,
                               const float* __restrict__ linb,
                               float* __restrict__ out, int n) {
    __shared__ float sW[6][F * F];   // Wi0, Wi1, Wc0, Wc1, Wo0, Wo1
    __shared__ float sBi[F], sBc[F], sBo[F], sWc2[F], sLw[F];
    __shared__ float sLb;

    int tid = threadIdx.x;
    for (int i = tid; i < F * F; i += blockDim.x) {
        sW[0][i] = Wx[0 * F * F + i];   // gate i, k=0
        sW[1][i] = Wx[1 * F * F + i];   // gate i, k=1
        sW[2][i] = Wx[4 * F * F + i];   // gate c, k=0
        sW[3][i] = Wx[5 * F * F + i];   // gate c, k=1
        sW[4][i] = Wx[6 * F * F + i];   // gate o, k=0
        sW[5][i] = Wx[7 * F * F + i];   // gate o, k=1
    }
    if (tid < F) {
        sBi[tid]  = bx[0 * F + tid] + bh[0 * F + tid] + bgate[0 * F + tid];
        sBc[tid]  = bx[2 * F + tid] + bh[2 * F + tid] + bgate[2 * F + tid];
        sBo[tid]  = bx[3 * F + tid] + bh[3 * F + tid] + bgate[3 * F + tid];
        sWc2[tid] = wc[2 * F + tid];
        sLw[tid]  = linw[tid];
        if (tid == 0) sLb = linb[0];
    }
    __syncthreads();

    int warp = tid >> 5;
    int lane = tid & 31;
    int base = (blockIdx.x * (blockDim.x >> 5) + warp) * 4;
    if (base >= n) return;

    // -------- gather phase: tx1 for 4 nodes into registers --------
    float xr[4], tr[4];
#pragma unroll
    for (int i = 0; i < 4; i++) {
        int nd = base + i;
        float acc = 0.0f, xv = 0.0f;
        if (nd < n) {                       // warp-uniform condition
            xv = x[nd * F + lane];
            int st = nd ? d_cnt[nd - 1] : 0;
            int en = d_cnt[nd];
            for (int b0 = st; b0 < en; b0 += 32) {
                int j = b0 + lane;
                int   sj = 0;
                float cj = 0.0f;
                if (j < en) { sj = d_esrc[j]; cj = d_ecoef[j]; }
                int mm = (min(32, en - b0) + 3) & ~3;
                for (int k = 0; k < mm; k += 4) {
                    int   s0 = __shfl_sync(0xffffffffu, sj, k);
                    int   s1 = __shfl_sync(0xffffffffu, sj, k + 1);
                    int   s2 = __shfl_sync(0xffffffffu, sj, k + 2);
                    int   s3 = __shfl_sync(0xffffffffu, sj, k + 3);
                    float c0 = __shfl_sync(0xffffffffu, cj, k);
                    float c1 = __shfl_sync(0xffffffffu, cj, k + 1);
                    float c2 = __shfl_sync(0xffffffffu, cj, k + 2);
                    float c3 = __shfl_sync(0xffffffffu, cj, k + 3);
                    float v0 = __ldg(&x[s0 * F + lane]);
                    float v1 = __ldg(&x[s1 * F + lane]);
                    float v2 = __ldg(&x[s2 * F + lane]);
                    float v3 = __ldg(&x[s3 * F + lane]);
                    acc += c0 * v0 + c1 * v1 + c2 * v2 + c3 * v3;
                }
            }
        }
        xr[i] = xv;
        tr[i] = acc;
    }

    // -------- gate phase: packed f32x2, 2 nodes per instruction --------
    float bi = sBi[lane], bc = sBc[lane], bo = sBo[lane];
    unsigned long long ai01 = pk2(bi, bi), ai23 = pk2(bi, bi);
    unsigned long long ac01 = pk2(bc, bc), ac23 = pk2(bc, bc);
    unsigned long long ao01 = pk2(bo, bo), ao23 = pk2(bo, bo);

#pragma unroll
    for (int f = 0; f < F; f++) {
        float w0 = sW[0][f * F + lane];
        float w1 = sW[1][f * F + lane];
        float w2 = sW[2][f * F + lane];
        float w3 = sW[3][f * F + lane];
        float w4 = sW[4][f * F + lane];
        float w5 = sW[5][f * F + lane];
        float xf0 = __shfl_sync(0xffffffffu, xr[0], f);
        float xf1 = __shfl_sync(0xffffffffu, xr[1], f);
        float xf2 = __shfl_sync(0xffffffffu, xr[2], f);
        float xf3 = __shfl_sync(0xffffffffu, xr[3], f);
        float tf0 = __shfl_sync(0xffffffffu, tr[0], f);
        float tf1 = __shfl_sync(0xffffffffu, tr[1], f);
        float tf2 = __shfl_sync(0xffffffffu, tr[2], f);
        float tf3 = __shfl_sync(0xffffffffu, tr[3], f);
        unsigned long long x01 = pk2(xf0, xf1), x23 = pk2(xf2, xf3);
        unsigned long long t01 = pk2(tf0, tf1), t23 = pk2(tf2, tf3);
        unsigned long long W0 = pk2(w0, w0), W1 = pk2(w1, w1);
        unsigned long long W2 = pk2(w2, w2), W3 = pk2(w3, w3);
        unsigned long long W4 = pk2(w4, w4), W5 = pk2(w5, w5);
        ai01 = fma2(x01, W0, fma2(t01, W1, ai01));
        ai23 = fma2(x23, W0, fma2(t23, W1, ai23));
        ac01 = fma2(x01, W2, fma2(t01, W3, ac01));
        ac23 = fma2(x23, W2, fma2(t23, W3, ac23));
        ao01 = fma2(x01, W4, fma2(t01, W5, ao01));
        ao23 = fma2(x23, W4, fma2(t23, W5, ao23));
    }

    float ai[4], ac[4], ao[4];
    upk2(ai01, ai[0], ai[1]); upk2(ai23, ai[2], ai[3]);
    upk2(ac01, ac[0], ac[1]); upk2(ac23, ac[2], ac[3]);
    upk2(ao01, ao[0], ao[1]); upk2(ao23, ao[2], ao[3]);

    float wcl = sWc2[lane], lwl = sLw[lane], lb = sLb;
#pragma unroll
    for (int i = 0; i < 4; i++) {
        int nd = base + i;
        if (nd >= n) break;                  // warp-uniform
        float I = 1.0f / (1.0f + expf(-ai[i]));
        float T = tanhf(ac[i]);
        float C = I * T;
        float O = 1.0f / (1.0f + expf(-(ao[i] + wcl * C)));
        float H = O * tanhf(C);
        float r = fmaxf(H, 0.0f) * lwl;
#pragma unroll
        for (int off = 16; off > 0; off >>= 1)
            r += __shfl_xor_sync(0xffffffffu, r, off);
        if (lane == 0) out[nd] = r + lb;
    }
}

// ---------------------------------------------------------------------------
extern "C" void kernel_launch(void* const* d_in, const int* in_sizes, int n_in,
                              void* d_out, int out_size) {
    const float* x     = (const float*)d_in[0];
    const void*  ei    = d_in[1];
    const float* ew    = (const float*)d_in[2];
    const float* Wx    = (const float*)d_in[3];
    const float* bx    = (const float*)d_in[4];
    // d_in[5] = Wh (dead: H_prev == 0)
    const float* bh    = (const float*)d_in[6];
    const float* wc    = (const float*)d_in[7];
    const float* bgate = (const float*)d_in[8];
    const float* linw  = (const float*)d_in[9];
    const float* linb  = (const float*)d_in[10];
    float*       out   = (float*)d_out;

    const int N = in_sizes[0] / F;
    const int E = in_sizes[2];

    const int B  = 256;
    const int NB = (N + SCAN_B - 1) / SCAN_B;   // scan blocks (<=1024)

    k_detect<<<1, 32>>>(ei, E, N);
    k_zero<<<(N + B - 1) / B, B>>>(N);
    k_prep<<<(E + B - 1) / B, B>>>(ei, ew, E, N);
    k_scan1<<<NB, SCAN_B>>>(N);
    k_scan2<<<1, 1024>>>(NB);
    k_scan3<<<NB, SCAN_B>>>(N);
    k_reorder<<<(E + B - 1) / B, B>>>(E);
    // 8 warps/block, 4 nodes/warp -> 32 nodes per block
    k_gather_gates<<<(N + 31) / 32, B>>>(x, Wx, bx, bh, wc, bgate, linw, linb,
                                         out, N);
}